// round 15
// baseline (speedup 1.0000x reference)
#include <cuda_runtime.h>
#include <cuda_bf16.h>
#include <cstdint>
#include <cstddef>

// Problem constants
#define BSZ   16384
#define DM    1024
#define RR    64
#define EE    4
#define LL    3
#define NV    256     // V columns (E*R) — no gate padding anymore
#define KW    256     // E*R

// ---------------------------------------------------------------------------
// Static device buffers (all bf16 compute; gates in fp32)
// ---------------------------------------------------------------------------
__device__ __align__(256) __nv_bfloat16  g_xh[(size_t)BSZ * DM];
__device__ __align__(256) __nv_bfloat16  g_xlo[(size_t)BSZ * DM];
__device__ __align__(256) float          g_Y[(size_t)BSZ * NV];
__device__ __align__(256) __nv_bfloat16  g_wh[(size_t)BSZ * KW];
__device__ __align__(256) __nv_bfloat16  g_W1h[LL * NV * DM];
__device__ __align__(256) __nv_bfloat16  g_W1l[LL * NV * DM];
__device__ __align__(256) __nv_bfloat16  g_Uh[LL * DM * KW];
__device__ __align__(256) __nv_bfloat16  g_Ul[LL * DM * KW];
__device__ __align__(256) float          g_gates[LL * (size_t)BSZ * EE];  // raw logits

// ---------------------------------------------------------------------------
// PTX helpers (baseline ISA only)
// ---------------------------------------------------------------------------
__device__ __forceinline__ uint32_t s2u(const void* p) {
    uint32_t a;
    asm("{ .reg .u64 t; cvta.to.shared.u64 t, %1; cvt.u32.u64 %0, t; }" : "=r"(a) : "l"(p));
    return a;
}
__device__ __forceinline__ void cpasync16(uint32_t dst, const void* src) {
    asm volatile("cp.async.cg.shared.global [%0], [%1], 16;" :: "r"(dst), "l"(src) : "memory");
}
#define CP_COMMIT() asm volatile("cp.async.commit_group;" ::: "memory")
#define CP_WAIT1()  asm volatile("cp.async.wait_group 1;" ::: "memory")

__device__ __forceinline__ void ldsm4(uint32_t* r, uint32_t addr) {
    asm volatile("ldmatrix.sync.aligned.m8n8.x4.shared.b16 {%0,%1,%2,%3}, [%4];"
                 : "=r"(r[0]), "=r"(r[1]), "=r"(r[2]), "=r"(r[3]) : "r"(addr));
}
__device__ __forceinline__ void mma_bf16(float* c, const uint32_t* a, const uint32_t* b) {
    asm volatile(
        "mma.sync.aligned.m16n8k16.row.col.f32.bf16.bf16.f32 "
        "{%0,%1,%2,%3}, {%4,%5,%6,%7}, {%8,%9}, {%0,%1,%2,%3};"
        : "+f"(c[0]), "+f"(c[1]), "+f"(c[2]), "+f"(c[3])
        : "r"(a[0]), "r"(a[1]), "r"(a[2]), "r"(a[3]), "r"(b[0]), "r"(b[1]));
}

// FMA-only tanh (no MUFU)
__device__ __forceinline__ float fast_tanh(float x) {
    float ax = fminf(fabsf(x), 9.0f);
    float z = ax * 2.885390082f;
    float k2 = z + 12582912.0f;
    int   ki = __float_as_int(k2) - 0x4B400000;
    float f  = z - (k2 - 12582912.0f);
    float p = 1.3333558e-3f;
    p = fmaf(p, f, 9.6181291e-3f);
    p = fmaf(p, f, 5.5504109e-2f);
    p = fmaf(p, f, 2.4022651e-1f);
    p = fmaf(p, f, 6.9314718e-1f);
    p = fmaf(p, f, 1.0f);
    float E = p * __int_as_float((ki + 127) << 23);
    float d = E + 1.0f;
    float r = __int_as_float(0x7EF311C3 - __float_as_int(d));
    r = r * fmaf(-d, r, 2.0f);
    r = r * fmaf(-d, r, 2.0f);
    r = r * fmaf(-d, r, 2.0f);
    float t = fmaf(-2.0f, r, 1.0f);
    return copysignf(t, x);
}

// ---------------------------------------------------------------------------
// GEMM1 (R14-proven geometry, now N=256 only): bf16 3-term.
// BM=128, BN=64, WN=32, BK=64 (pitch 144), 2-stage cp.async, 2 CTAs/SM.
// ---------------------------------------------------------------------------
__global__ void __launch_bounds__(256, 2)
gemm1_bf16(const __nv_bfloat16* __restrict__ Agh, const __nv_bfloat16* __restrict__ Agl,
           const __nv_bfloat16* __restrict__ Bgh, const __nv_bfloat16* __restrict__ Bgl,
           int bRowOff, float* __restrict__ Cout)
{
    constexpr int BM = 128, BN = 64, WN = 32, BK = 64, KTOT = DM;
    constexpr int MF = 2, NF = WN / 8, KS = BK / 16, KCH = KTOT / BK;
    constexpr int PITCH = 2 * BK + 16;       // 144
    constexpr int SA = BM * PITCH, SB = BN * PITCH, SST = 2 * SA + 2 * SB;

    extern __shared__ __align__(128) char smem[];
    const uint32_t sbase = s2u(smem);

    const int tid = threadIdx.x, lane = tid & 31, wid = tid >> 5;
    const int wm = wid & 3, wn = wid >> 2;
    const int m0 = blockIdx.y * BM;
    const int n0 = bRowOff + blockIdx.x * BN;
    const int c0 = blockIdx.x * BN;
    const int K = KTOT;

    float acc[MF][NF][4];
#pragma unroll
    for (int i = 0; i < MF; ++i)
#pragma unroll
        for (int j = 0; j < NF; ++j)
#pragma unroll
            for (int p = 0; p < 4; ++p) acc[i][j][p] = 0.f;

    auto load_stage = [&](int st, int kt) {
        const uint32_t base = sbase + st * SST;
        const int kk = kt * BK;
        constexpr int CPR = BK / 8;
#pragma unroll
        for (int c = tid; c < BM * CPR; c += 256) {
            const int row = c / CPR, cc = c % CPR;
            const size_t g = (size_t)(m0 + row) * K + kk + cc * 8;
            const uint32_t s = row * PITCH + cc * 16;
            cpasync16(base + s,      Agh + g);
            cpasync16(base + SA + s, Agl + g);
        }
#pragma unroll
        for (int c = tid; c < BN * CPR; c += 256) {
            const int row = c / CPR, cc = c % CPR;
            const size_t g = (size_t)(n0 + row) * K + kk + cc * 8;
            const uint32_t s = row * PITCH + cc * 16;
            cpasync16(base + 2 * SA + s,      Bgh + g);
            cpasync16(base + 2 * SA + SB + s, Bgl + g);
        }
    };

    load_stage(0, 0);
    CP_COMMIT();

    const int arow = wm * 32 + (lane & 15);
    const int brow = wn * WN + (lane & 7) + ((lane >> 4) << 3);
    const uint32_t aoff = (uint32_t)arow * PITCH + ((lane >> 4) << 4);
    const uint32_t boff = (uint32_t)brow * PITCH + (((lane >> 3) & 1) << 4);

    for (int kt = 0; kt < KCH; ++kt) {
        if (kt + 1 < KCH) load_stage((kt + 1) & 1, kt + 1);
        CP_COMMIT();
        CP_WAIT1();
        __syncthreads();

        const uint32_t sb2 = sbase + (kt & 1) * SST;
        const uint32_t ab = sb2 + aoff;
        const uint32_t bb = sb2 + 2 * SA + boff;

#pragma unroll
        for (int ks = 0; ks < KS; ++ks) {
            uint32_t ah[MF][4], al[MF][4];
#pragma unroll
            for (int mf = 0; mf < MF; ++mf) {
                const uint32_t off = ab + mf * 16 * PITCH + ks * 32;
                ldsm4(ah[mf], off);
                ldsm4(al[mf], off + SA);
            }
            uint32_t bh[NF][2], bl[NF][2];
#pragma unroll
            for (int nf2 = 0; nf2 < NF / 2; ++nf2) {
                const uint32_t off = bb + nf2 * 16 * PITCH + ks * 32;
                uint32_t t[4];
                ldsm4(t, off);
                bh[2 * nf2][0] = t[0]; bh[2 * nf2][1] = t[1];
                bh[2 * nf2 + 1][0] = t[2]; bh[2 * nf2 + 1][1] = t[3];
                ldsm4(t, off + SB);
                bl[2 * nf2][0] = t[0]; bl[2 * nf2][1] = t[1];
                bl[2 * nf2 + 1][0] = t[2]; bl[2 * nf2 + 1][1] = t[3];
            }
#pragma unroll
            for (int mf = 0; mf < MF; ++mf)
#pragma unroll
                for (int nf = 0; nf < NF; ++nf) {
                    mma_bf16(acc[mf][nf], ah[mf], bh[nf]);
                    mma_bf16(acc[mf][nf], ah[mf], bl[nf]);
                    mma_bf16(acc[mf][nf], al[mf], bh[nf]);
                }
        }
        __syncthreads();
    }

#pragma unroll
    for (int mf = 0; mf < MF; ++mf)
#pragma unroll
        for (int p = 0; p < 2; ++p) {
            const int m = m0 + wm * 32 + mf * 16 + (lane >> 2) + p * 8;
#pragma unroll
            for (int nf = 0; nf < NF; ++nf) {
                const int col = c0 + wn * WN + nf * 8 + (lane & 3) * 2;
                *reinterpret_cast<float2*>(Cout + (size_t)m * NV + col) =
                    make_float2(acc[mf][nf][p * 2], acc[mf][nf][p * 2 + 1]);
            }
        }
}

// ---------------------------------------------------------------------------
// GEMM2 (R14-proven): bf16 2-term, A single (wh), B split (Uh+Ul).
// BM=128, BN=128, WN=64, BK=32 (pitch 80), 2-stage cp.async, 2 CTAs/SM.
// Epilogue: o = (xh+xlo) + x0*(D+bias).
// MODE 1: writes bf16 xh/xlo = split(o) AND accumulates next-layer gate
//         logits (fp32, exact) via shfl-reduce + atomicAdd.
// MODE 2: writes fp32 o to Cout (last layer, no gates).
// ---------------------------------------------------------------------------
template <int MODE>
__global__ void __launch_bounds__(256, 2)
gemm2_bf16(const __nv_bfloat16* __restrict__ Ag,
           const __nv_bfloat16* __restrict__ Bgh, const __nv_bfloat16* __restrict__ Bgl,
           int bRowOff, float* __restrict__ Cout,
           const float* __restrict__ x0, const float* __restrict__ bias,
           __nv_bfloat16* __restrict__ xh, __nv_bfloat16* __restrict__ xl,
           const float* __restrict__ gwp, float* __restrict__ gnext)
{
    constexpr int BM = 128, BN = 128, WN = 64, BK = 32, KTOT = KW;
    constexpr int MF = 2, NF = WN / 8, KS = BK / 16, KCH = KTOT / BK;
    constexpr int PITCH = 2 * BK + 16;       // 80
    constexpr int SA = BM * PITCH, SB = BN * PITCH, SST = SA + 2 * SB;

    extern __shared__ __align__(128) char smem[];
    const uint32_t sbase = s2u(smem);
    float* gwsf = reinterpret_cast<float*>(smem + 2 * SST);   // [128 cols][4 e]

    const int tid = threadIdx.x, lane = tid & 31, wid = tid >> 5;
    const int wm = wid & 3, wn = wid >> 2;
    const int m0 = blockIdx.y * BM;
    const int n0 = bRowOff + blockIdx.x * BN;
    const int c0 = blockIdx.x * BN;
    const int K = KTOT;

    if constexpr (MODE == 1) {
        // Stage gw columns for this CTA's 128 output cols: gws[c][e]
        for (int idx = tid; idx < BN * EE; idx += 256) {
            const int c = idx >> 2, e = idx & 3;
            gwsf[c * 4 + e] = gwp[(size_t)e * DM + c0 + c];
        }
    }

    float acc[MF][NF][4];
#pragma unroll
    for (int i = 0; i < MF; ++i)
#pragma unroll
        for (int j = 0; j < NF; ++j)
#pragma unroll
            for (int p = 0; p < 4; ++p) acc[i][j][p] = 0.f;

    auto load_stage = [&](int st, int kt) {
        const uint32_t base = sbase + st * SST;
        const int kk = kt * BK;
        constexpr int CPR = BK / 8;      // 4
#pragma unroll
        for (int c = tid; c < BM * CPR; c += 256) {
            const int row = c / CPR, cc = c % CPR;
            cpasync16(base + row * PITCH + cc * 16,
                      Ag + (size_t)(m0 + row) * K + kk + cc * 8);
        }
#pragma unroll
        for (int c = tid; c < BN * CPR; c += 256) {
            const int row = c / CPR, cc = c % CPR;
            const size_t g = (size_t)(n0 + row) * K + kk + cc * 8;
            const uint32_t s = row * PITCH + cc * 16;
            cpasync16(base + SA + s,      Bgh + g);
            cpasync16(base + SA + SB + s, Bgl + g);
        }
    };

    load_stage(0, 0);
    CP_COMMIT();

    const int arow = wm * 32 + (lane & 15);
    const int brow = wn * WN + (lane & 7) + ((lane >> 4) << 3);
    const uint32_t aoff = (uint32_t)arow * PITCH + ((lane >> 4) << 4);
    const uint32_t boff = (uint32_t)brow * PITCH + (((lane >> 3) & 1) << 4);

    for (int kt = 0; kt < KCH; ++kt) {
        if (kt + 1 < KCH) load_stage((kt + 1) & 1, kt + 1);
        CP_COMMIT();
        CP_WAIT1();
        __syncthreads();

        const uint32_t sb2 = sbase + (kt & 1) * SST;
        const uint32_t ab = sb2 + aoff;
        const uint32_t bb = sb2 + SA + boff;

#pragma unroll
        for (int ks = 0; ks < KS; ++ks) {
            uint32_t af[MF][4];
#pragma unroll
            for (int mf = 0; mf < MF; ++mf)
                ldsm4(af[mf], ab + mf * 16 * PITCH + ks * 32);
            uint32_t bh[NF][2], bl[NF][2];
#pragma unroll
            for (int nf2 = 0; nf2 < NF / 2; ++nf2) {
                const uint32_t off = bb + nf2 * 16 * PITCH + ks * 32;
                uint32_t t[4];
                ldsm4(t, off);
                bh[2 * nf2][0] = t[0]; bh[2 * nf2][1] = t[1];
                bh[2 * nf2 + 1][0] = t[2]; bh[2 * nf2 + 1][1] = t[3];
                ldsm4(t, off + SB);
                bl[2 * nf2][0] = t[0]; bl[2 * nf2][1] = t[1];
                bl[2 * nf2 + 1][0] = t[2]; bl[2 * nf2 + 1][1] = t[3];
            }
#pragma unroll
            for (int mf = 0; mf < MF; ++mf)
#pragma unroll
                for (int nf = 0; nf < NF; ++nf)
                    mma_bf16(acc[mf][nf], af[mf], bh[nf]);
#pragma unroll
            for (int mf = 0; mf < MF; ++mf)
#pragma unroll
                for (int nf = 0; nf < NF; ++nf)
                    mma_bf16(acc[mf][nf], af[mf], bl[nf]);
        }
        __syncthreads();
    }

    // Epilogue: o = (xh+xlo) + x0*(D+bias); optional gate-logit accumulation
#pragma unroll
    for (int mf = 0; mf < MF; ++mf)
#pragma unroll
        for (int p = 0; p < 2; ++p) {
            const int m = m0 + wm * 32 + mf * 16 + (lane >> 2) + p * 8;
            float gpart0 = 0.f, gpart1 = 0.f, gpart2 = 0.f, gpart3 = 0.f;
#pragma unroll
            for (int nf = 0; nf < NF; ++nf) {
                const int colloc = wn * WN + nf * 8 + (lane & 3) * 2;  // 0..127
                const int col = c0 + colloc;
                const size_t off = (size_t)m * DM + col;
                const float v0 = acc[mf][nf][p * 2];
                const float v1 = acc[mf][nf][p * 2 + 1];
                const float2 xz = *reinterpret_cast<const float2*>(x0 + off);
                const float2 bb2 = *reinterpret_cast<const float2*>(bias + col);
                const __nv_bfloat162 hv = *reinterpret_cast<const __nv_bfloat162*>(xh + off);
                const __nv_bfloat162 lv = *reinterpret_cast<const __nv_bfloat162*>(xl + off);
                const float xp0 = __bfloat162float(hv.x) + __bfloat162float(lv.x);
                const float xp1 = __bfloat162float(hv.y) + __bfloat162float(lv.y);
                const float o0 = fmaf(xz.x, v0 + bb2.x, xp0);
                const float o1 = fmaf(xz.y, v1 + bb2.y, xp1);
                if constexpr (MODE == 1) {
                    const __nv_bfloat16 h0 = __float2bfloat16(o0);
                    const __nv_bfloat16 h1 = __float2bfloat16(o1);
                    __nv_bfloat162 hp; hp.x = h0; hp.y = h1;
                    *reinterpret_cast<__nv_bfloat162*>(xh + off) = hp;
                    __nv_bfloat162 lp;
                    lp.x = __float2bfloat16(o0 - __bfloat162float(h0));
                    lp.y = __float2bfloat16(o1 - __bfloat162float(h1));
                    *reinterpret_cast<__nv_bfloat162*>(xl + off) = lp;
                    // gate logit partials (exact fp32, from pre-split o)
                    const float4 ga = *reinterpret_cast<const float4*>(gwsf + colloc * 4);
                    const float4 gb = *reinterpret_cast<const float4*>(gwsf + (colloc + 1) * 4);
                    gpart0 = fmaf(o0, ga.x, fmaf(o1, gb.x, gpart0));
                    gpart1 = fmaf(o0, ga.y, fmaf(o1, gb.y, gpart1));
                    gpart2 = fmaf(o0, ga.z, fmaf(o1, gb.z, gpart2));
                    gpart3 = fmaf(o0, ga.w, fmaf(o1, gb.w, gpart3));
                } else {
                    *reinterpret_cast<float2*>(Cout + off) = make_float2(o0, o1);
                }
            }
            if constexpr (MODE == 1) {
                // reduce across quad (lanes with same row m: lane&3 varies)
#pragma unroll
                for (int sh = 1; sh <= 2; sh <<= 1) {
                    gpart0 += __shfl_xor_sync(0xffffffffu, gpart0, sh);
                    gpart1 += __shfl_xor_sync(0xffffffffu, gpart1, sh);
                    gpart2 += __shfl_xor_sync(0xffffffffu, gpart2, sh);
                    gpart3 += __shfl_xor_sync(0xffffffffu, gpart3, sh);
                }
                if ((lane & 3) == 0) {
                    atomicAdd(gnext + (size_t)m * EE + 0, gpart0);
                    atomicAdd(gnext + (size_t)m * EE + 1, gpart1);
                    atomicAdd(gnext + (size_t)m * EE + 2, gpart2);
                    atomicAdd(gnext + (size_t)m * EE + 3, gpart3);
                }
            }
        }
}

// ---------------------------------------------------------------------------
// Mix kernel: vt=tanh(Y) -> v2=tanh(C vt) -> softmax(gates buf) -> bf16 wh
// ---------------------------------------------------------------------------
__global__ void __launch_bounds__(256) mix_kernel(const float* __restrict__ Y,
                                                  const float* __restrict__ Cl,
                                                  const float* __restrict__ gates,
                                                  __nv_bfloat16* __restrict__ Wh)
{
    extern __shared__ float Cs[];          // 64 KB: Cs[(e*64+s)*64 + r] = C[e,r,s]
    __shared__ float vt[8][EE * RR];
    __shared__ float gs[8][EE];

    const int tid = threadIdx.x;
    for (int idx = tid; idx < EE * RR * RR; idx += 256) {
        int e = idx >> 12, rem = idx & 4095, s = rem >> 6, r = rem & 63;
        Cs[idx] = Cl[((size_t)e * RR + r) * RR + s];
    }
    __syncthreads();

    const int e = tid >> 6;
    const float* cp = Cs + e * (RR * RR) + (tid & 63);
    const int row0 = blockIdx.x * 64;

    for (int it = 0; it < 8; ++it) {
        const int row = row0 + it * 8;
#pragma unroll
        for (int q = 0; q < 8; ++q)
            vt[q][tid] = fast_tanh(Y[(size_t)(row + q) * NV + tid]);
        if (tid < 8) {
            const float4 lg = *reinterpret_cast<const float4*>(gates + (size_t)(row + tid) * EE);
            const float mx = fmaxf(fmaxf(lg.x, lg.y), fmaxf(lg.z, lg.w));
            const float e0 = __expf(lg.x - mx), e1 = __expf(lg.y - mx);
            const float e2 = __expf(lg.z - mx), e3 = __expf(lg.w - mx);
            const float inv = __frcp_rn(e0 + e1 + e2 + e3);
            gs[tid][0] = e0 * inv; gs[tid][1] = e1 * inv;
            gs[tid][2] = e2 * inv; gs[tid][3] = e3 * inv;
        }
        __syncthreads();

        float a[8];
#pragma unroll
        for (int q = 0; q < 8; ++q) a[q] = 0.f;
#pragma unroll
        for (int s = 0; s < RR; ++s) {
            const float c = cp[s * RR];
#pragma unroll
            for (int q = 0; q < 8; ++q)
                a[q] = fmaf(c, vt[q][e * RR + s], a[q]);
        }
#pragma unroll
        for (int q = 0; q < 8; ++q) {
            const float w = gs[q][e] * fast_tanh(a[q]);
            Wh[(size_t)(row + q) * KW + tid] = __float2bfloat16(w);
        }
        __syncthreads();
    }
}

// ---------------------------------------------------------------------------
// Zero gates, conversion + layer-0 gates, weight packing
// ---------------------------------------------------------------------------
__global__ void zero_gates_kernel(float* __restrict__ g) {
    const int idx = blockIdx.x * blockDim.x + threadIdx.x;
    if (idx < LL * BSZ * EE) g[idx] = 0.f;
}

__global__ void conv_kernel(const float* __restrict__ x,
                            const float* __restrict__ gw,
                            __nv_bfloat16* __restrict__ xh,
                            __nv_bfloat16* __restrict__ xl,
                            float* __restrict__ g0) {
    const size_t i = ((size_t)blockIdx.x * blockDim.x + threadIdx.x) * 4;
    const float4 v = *reinterpret_cast<const float4*>(x + i);
    __nv_bfloat16 h0 = __float2bfloat16(v.x), h1 = __float2bfloat16(v.y);
    __nv_bfloat16 h2 = __float2bfloat16(v.z), h3 = __float2bfloat16(v.w);
    __nv_bfloat162 hp0; hp0.x = h0; hp0.y = h1;
    __nv_bfloat162 hp1; hp1.x = h2; hp1.y = h3;
    *reinterpret_cast<__nv_bfloat162*>(xh + i)     = hp0;
    *reinterpret_cast<__nv_bfloat162*>(xh + i + 2) = hp1;
    __nv_bfloat162 lp0, lp1;
    lp0.x = __float2bfloat16(v.x - __bfloat162float(h0));
    lp0.y = __float2bfloat16(v.y - __bfloat162float(h1));
    lp1.x = __float2bfloat16(v.z - __bfloat162float(h2));
    lp1.y = __float2bfloat16(v.w - __bfloat162float(h3));
    *reinterpret_cast<__nv_bfloat162*>(xl + i)     = lp0;
    *reinterpret_cast<__nv_bfloat162*>(xl + i + 2) = lp1;

    // layer-0 gate logits: warp covers 128 consecutive elems = one row slice
    const int row = (int)(i / DM);
    const int col = (int)(i % DM);
    float gp[EE];
#pragma unroll
    for (int e = 0; e < EE; ++e) {
        const float* gwr = gw + (size_t)e * DM + col;
        gp[e] = v.x * gwr[0] + v.y * gwr[1] + v.z * gwr[2] + v.w * gwr[3];
    }
#pragma unroll
    for (int sh = 16; sh >= 1; sh >>= 1)
#pragma unroll
        for (int e = 0; e < EE; ++e)
            gp[e] += __shfl_xor_sync(0xffffffffu, gp[e], sh);
    if ((threadIdx.x & 31) == 0) {
#pragma unroll
        for (int e = 0; e < EE; ++e)
            atomicAdd(g0 + (size_t)row * EE + e, gp[e]);
    }
}

__global__ void pack_w1_kernel(const float* __restrict__ V,
                               __nv_bfloat16* __restrict__ Wh, __nv_bfloat16* __restrict__ Wl) {
    const int idx = blockIdx.x * blockDim.x + threadIdx.x;
    if (idx >= LL * NV * DM) return;
    const int i = idx / (NV * DM);
    const int rem = idx % (NV * DM);
    const int n = rem / DM, d = rem % DM;
    const float v = V[(((size_t)i * EE + (n >> 6)) * DM + d) * RR + (n & 63)];
    const __nv_bfloat16 h = __float2bfloat16(v);
    Wh[idx] = h;
    Wl[idx] = __float2bfloat16(v - __bfloat162float(h));
}

__global__ void pack_u_kernel(const float* __restrict__ U,
                              __nv_bfloat16* __restrict__ Uh, __nv_bfloat16* __restrict__ Ul) {
    const int idx = blockIdx.x * blockDim.x + threadIdx.x;
    if (idx >= LL * DM * KW) return;
    const int i = idx / (DM * KW);
    const int rem = idx % (DM * KW);
    const int d = rem / KW, k = rem % KW;
    const float v = U[(((size_t)i * EE + (k >> 6)) * DM + d) * RR + (k & 63)];
    const __nv_bfloat16 h = __float2bfloat16(v);
    Uh[idx] = h;
    Ul[idx] = __float2bfloat16(v - __bfloat162float(h));
}

// ---------------------------------------------------------------------------
// Launch
// ---------------------------------------------------------------------------
extern "C" void kernel_launch(void* const* d_in, const int* in_sizes, int n_in,
                              void* d_out, int out_size) {
    const float* x0   = (const float*)d_in[0];
    const float* U    = (const float*)d_in[1];
    const float* V    = (const float*)d_in[2];
    const float* C    = (const float*)d_in[3];
    const float* gw   = (const float*)d_in[4];
    const float* bias = (const float*)d_in[5];
    float* out = (float*)d_out;

    float *Y = nullptr, *gates = nullptr;
    __nv_bfloat16 *xh, *xl, *wh, *w1h, *w1l, *uh, *ul;
    cudaGetSymbolAddress((void**)&Y,     g_Y);
    cudaGetSymbolAddress((void**)&gates, g_gates);
    cudaGetSymbolAddress((void**)&xh,  g_xh);
    cudaGetSymbolAddress((void**)&xl,  g_xlo);
    cudaGetSymbolAddress((void**)&wh,  g_wh);
    cudaGetSymbolAddress((void**)&w1h, g_W1h);
    cudaGetSymbolAddress((void**)&w1l, g_W1l);
    cudaGetSymbolAddress((void**)&uh,  g_Uh);
    cudaGetSymbolAddress((void**)&ul,  g_Ul);

    constexpr int SMEM1 = 2 * (2 * 128 * 144 + 2 * 64 * 144);           // 110592
    constexpr int SMEM2 = 2 * (128 * 80 + 2 * 128 * 80) + 128 * EE * 4; // 61440+2048
    cudaFuncSetAttribute((const void*)gemm1_bf16,
                         cudaFuncAttributeMaxDynamicSharedMemorySize, SMEM1);
    cudaFuncSetAttribute((const void*)gemm2_bf16<1>,
                         cudaFuncAttributeMaxDynamicSharedMemorySize, SMEM2);
    cudaFuncSetAttribute((const void*)gemm2_bf16<2>,
                         cudaFuncAttributeMaxDynamicSharedMemorySize, SMEM2);
    cudaFuncSetAttribute((const void*)mix_kernel,
                         cudaFuncAttributeMaxDynamicSharedMemorySize, EE * RR * RR * 4);

    // Zero gate logits (inside the graph — replay-safe), pack, convert
    zero_gates_kernel<<<(LL * BSZ * EE + 255) / 256, 256>>>(gates);
    pack_w1_kernel<<<(LL * NV * DM + 255) / 256, 256>>>(V, w1h, w1l);
    pack_u_kernel<<<(LL * DM * KW + 255) / 256, 256>>>(U, uh, ul);
    conv_kernel<<<(BSZ * DM / 4) / 256, 256>>>(x0, gw, xh, xl, gates);

    for (int i = 0; i < LL; ++i) {
        // GEMM1: Y[B,256] = x @ V^T (no gate padding)
        gemm1_bf16<<<dim3(NV / 64, BSZ / 128), 256, SMEM1>>>(
            xh, xl, w1h, w1l, i * NV, Y);

        // Mix: tanh -> C -> tanh -> softmax(gates[i]) -> bf16 wh
        mix_kernel<<<BSZ / 64, 256, EE * RR * RR * 4>>>(
            Y, C + (size_t)i * EE * RR * RR, gates + (size_t)i * BSZ * EE, wh);

        // GEMM2 + fused epilogue (+ next-layer gate logits for MODE 1)
        if (i < LL - 1) {
            gemm2_bf16<1><<<dim3(DM / 128, BSZ / 128), 256, SMEM2>>>(
                wh, uh, ul, i * DM,
                nullptr, x0, bias + (size_t)i * DM, xh, xl,
                gw, gates + (size_t)(i + 1) * BSZ * EE);
        } else {
            gemm2_bf16<2><<<dim3(DM / 128, BSZ / 128), 256, SMEM2>>>(
                wh, uh, ul, i * DM,
                out, x0, bias + (size_t)i * DM, xh, xl,
                gw, nullptr);
        }
    }
}

// round 16
// speedup vs baseline: 1.2113x; 1.2113x over previous
#include <cuda_runtime.h>
#include <cuda_bf16.h>
#include <cstdint>
#include <cstddef>

// Problem constants
#define BSZ   16384
#define DM    1024
#define RR    64
#define EE    4
#define LL    3
#define NPAD  320     // 256 V cols + 4 gate cols, padded to 5*64
#define KW    256     // E*R

// ---------------------------------------------------------------------------
// Static device buffers (all bf16)
// ---------------------------------------------------------------------------
__device__ __align__(256) __nv_bfloat16  g_xh[(size_t)BSZ * DM];      // bf16 hi of x_l
__device__ __align__(256) __nv_bfloat16  g_xlo[(size_t)BSZ * DM];     // bf16 lo of x_l
__device__ __align__(256) float          g_Y[(size_t)BSZ * NPAD];
__device__ __align__(256) __nv_bfloat16  g_wh[(size_t)BSZ * KW];      // bf16 w (rounded)
__device__ __align__(256) __nv_bfloat16  g_W1h[LL * NPAD * DM];       // [n][d] rows
__device__ __align__(256) __nv_bfloat16  g_W1l[LL * NPAD * DM];
__device__ __align__(256) __nv_bfloat16  g_Uh[LL * DM * KW];          // [d][k] rows
__device__ __align__(256) __nv_bfloat16  g_Ul[LL * DM * KW];

// ---------------------------------------------------------------------------
// PTX helpers (baseline ISA only)
// ---------------------------------------------------------------------------
__device__ __forceinline__ uint32_t s2u(const void* p) {
    uint32_t a;
    asm("{ .reg .u64 t; cvta.to.shared.u64 t, %1; cvt.u32.u64 %0, t; }" : "=r"(a) : "l"(p));
    return a;
}
__device__ __forceinline__ void cpasync16(uint32_t dst, const void* src) {
    asm volatile("cp.async.cg.shared.global [%0], [%1], 16;" :: "r"(dst), "l"(src) : "memory");
}
#define CP_COMMIT() asm volatile("cp.async.commit_group;" ::: "memory")
#define CP_WAIT1()  asm volatile("cp.async.wait_group 1;" ::: "memory")
#define CP_WAIT2()  asm volatile("cp.async.wait_group 2;" ::: "memory")

__device__ __forceinline__ void ldsm4(uint32_t* r, uint32_t addr) {
    asm volatile("ldmatrix.sync.aligned.m8n8.x4.shared.b16 {%0,%1,%2,%3}, [%4];"
                 : "=r"(r[0]), "=r"(r[1]), "=r"(r[2]), "=r"(r[3]) : "r"(addr));
}
__device__ __forceinline__ void mma_bf16(float* c, const uint32_t* a, const uint32_t* b) {
    asm volatile(
        "mma.sync.aligned.m16n8k16.row.col.f32.bf16.bf16.f32 "
        "{%0,%1,%2,%3}, {%4,%5,%6,%7}, {%8,%9}, {%0,%1,%2,%3};"
        : "+f"(c[0]), "+f"(c[1]), "+f"(c[2]), "+f"(c[3])
        : "r"(a[0]), "r"(a[1]), "r"(a[2]), "r"(a[3]), "r"(b[0]), "r"(b[1]));
}

// FMA-only tanh (no MUFU)
__device__ __forceinline__ float fast_tanh(float x) {
    float ax = fminf(fabsf(x), 9.0f);
    float z = ax * 2.885390082f;
    float k2 = z + 12582912.0f;
    int   ki = __float_as_int(k2) - 0x4B400000;
    float f  = z - (k2 - 12582912.0f);
    float p = 1.3333558e-3f;
    p = fmaf(p, f, 9.6181291e-3f);
    p = fmaf(p, f, 5.5504109e-2f);
    p = fmaf(p, f, 2.4022651e-1f);
    p = fmaf(p, f, 6.9314718e-1f);
    p = fmaf(p, f, 1.0f);
    float E = p * __int_as_float((ki + 127) << 23);
    float d = E + 1.0f;
    float r = __int_as_float(0x7EF311C3 - __float_as_int(d));
    r = r * fmaf(-d, r, 2.0f);
    r = r * fmaf(-d, r, 2.0f);
    r = r * fmaf(-d, r, 2.0f);
    float t = fmaf(-2.0f, r, 1.0f);
    return copysignf(t, x);
}

// ---------------------------------------------------------------------------
// GEMM1 (R14-proven, 107us): bf16 3-term, D = (Ah+Al)@(Bh+Bl)^T (drop Al*Bl)
// BM=128, BN=64, WN=32, BK=64 (pitch 144), 2-stage cp.async, 2 CTAs/SM.
// ---------------------------------------------------------------------------
__global__ void __launch_bounds__(256, 2)
gemm1_bf16(const __nv_bfloat16* __restrict__ Agh, const __nv_bfloat16* __restrict__ Agl,
           const __nv_bfloat16* __restrict__ Bgh, const __nv_bfloat16* __restrict__ Bgl,
           int bRowOff, float* __restrict__ Cout)
{
    constexpr int BM = 128, BN = 64, WN = 32, BK = 64, KTOT = DM;
    constexpr int MF = 2, NF = WN / 8, KS = BK / 16, KCH = KTOT / BK;
    constexpr int PITCH = 2 * BK + 16;       // 144
    constexpr int SA = BM * PITCH, SB = BN * PITCH, SST = 2 * SA + 2 * SB;

    extern __shared__ __align__(128) char smem[];
    const uint32_t sbase = s2u(smem);

    const int tid = threadIdx.x, lane = tid & 31, wid = tid >> 5;
    const int wm = wid & 3, wn = wid >> 2;
    const int m0 = blockIdx.y * BM;
    const int n0 = bRowOff + blockIdx.x * BN;
    const int c0 = blockIdx.x * BN;
    const int K = KTOT;

    float acc[MF][NF][4];
#pragma unroll
    for (int i = 0; i < MF; ++i)
#pragma unroll
        for (int j = 0; j < NF; ++j)
#pragma unroll
            for (int p = 0; p < 4; ++p) acc[i][j][p] = 0.f;

    auto load_stage = [&](int st, int kt) {
        const uint32_t base = sbase + st * SST;
        const int kk = kt * BK;
        constexpr int CPR = BK / 8;
#pragma unroll
        for (int c = tid; c < BM * CPR; c += 256) {
            const int row = c / CPR, cc = c % CPR;
            const size_t g = (size_t)(m0 + row) * K + kk + cc * 8;
            const uint32_t s = row * PITCH + cc * 16;
            cpasync16(base + s,      Agh + g);
            cpasync16(base + SA + s, Agl + g);
        }
#pragma unroll
        for (int c = tid; c < BN * CPR; c += 256) {
            const int row = c / CPR, cc = c % CPR;
            const size_t g = (size_t)(n0 + row) * K + kk + cc * 8;
            const uint32_t s = row * PITCH + cc * 16;
            cpasync16(base + 2 * SA + s,      Bgh + g);
            cpasync16(base + 2 * SA + SB + s, Bgl + g);
        }
    };

    load_stage(0, 0);
    CP_COMMIT();

    const int arow = wm * 32 + (lane & 15);
    const int brow = wn * WN + (lane & 7) + ((lane >> 4) << 3);
    const uint32_t aoff = (uint32_t)arow * PITCH + ((lane >> 4) << 4);
    const uint32_t boff = (uint32_t)brow * PITCH + (((lane >> 3) & 1) << 4);

    for (int kt = 0; kt < KCH; ++kt) {
        if (kt + 1 < KCH) load_stage((kt + 1) & 1, kt + 1);
        CP_COMMIT();
        CP_WAIT1();
        __syncthreads();

        const uint32_t sb2 = sbase + (kt & 1) * SST;
        const uint32_t ab = sb2 + aoff;
        const uint32_t bb = sb2 + 2 * SA + boff;

#pragma unroll
        for (int ks = 0; ks < KS; ++ks) {
            uint32_t ah[MF][4], al[MF][4];
#pragma unroll
            for (int mf = 0; mf < MF; ++mf) {
                const uint32_t off = ab + mf * 16 * PITCH + ks * 32;
                ldsm4(ah[mf], off);
                ldsm4(al[mf], off + SA);
            }
            uint32_t bh[NF][2], bl[NF][2];
#pragma unroll
            for (int nf2 = 0; nf2 < NF / 2; ++nf2) {
                const uint32_t off = bb + nf2 * 16 * PITCH + ks * 32;
                uint32_t t[4];
                ldsm4(t, off);
                bh[2 * nf2][0] = t[0]; bh[2 * nf2][1] = t[1];
                bh[2 * nf2 + 1][0] = t[2]; bh[2 * nf2 + 1][1] = t[3];
                ldsm4(t, off + SB);
                bl[2 * nf2][0] = t[0]; bl[2 * nf2][1] = t[1];
                bl[2 * nf2 + 1][0] = t[2]; bl[2 * nf2 + 1][1] = t[3];
            }
#pragma unroll
            for (int mf = 0; mf < MF; ++mf)
#pragma unroll
                for (int nf = 0; nf < NF; ++nf) {
                    mma_bf16(acc[mf][nf], ah[mf], bh[nf]);
                    mma_bf16(acc[mf][nf], ah[mf], bl[nf]);
                    mma_bf16(acc[mf][nf], al[mf], bh[nf]);
                }
        }
        __syncthreads();
    }

#pragma unroll
    for (int mf = 0; mf < MF; ++mf)
#pragma unroll
        for (int p = 0; p < 2; ++p) {
            const int m = m0 + wm * 32 + mf * 16 + (lane >> 2) + p * 8;
#pragma unroll
            for (int nf = 0; nf < NF; ++nf) {
                const int col = c0 + wn * WN + nf * 8 + (lane & 3) * 2;
                *reinterpret_cast<float2*>(Cout + (size_t)m * NPAD + col) =
                    make_float2(acc[mf][nf][p * 2], acc[mf][nf][p * 2 + 1]);
            }
        }
}

// ---------------------------------------------------------------------------
// GEMM2: bf16 2-term (A single wh, B split Uh+Ul), NOW 3-STAGE pipeline.
// BM=128, BN=128, WN=64, BK=32 (pitch 80), 3 stages (92160 B), 2 CTAs/SM.
// Epilogue: o = (xh+xlo) + x0*(D+bias); MODE 1 writes bf16 xh/xlo = split(o),
// MODE 2 writes fp32 o to Cout.
// ---------------------------------------------------------------------------
template <int MODE>
__global__ void __launch_bounds__(256, 2)
gemm2_bf16(const __nv_bfloat16* __restrict__ Ag,
           const __nv_bfloat16* __restrict__ Bgh, const __nv_bfloat16* __restrict__ Bgl,
           int bRowOff, float* __restrict__ Cout,
           const float* __restrict__ x0, const float* __restrict__ bias,
           __nv_bfloat16* __restrict__ xh, __nv_bfloat16* __restrict__ xl)
{
    constexpr int BM = 128, BN = 128, WN = 64, BK = 32, KTOT = KW, STAGES = 3;
    constexpr int MF = 2, NF = WN / 8, KS = BK / 16, KCH = KTOT / BK;
    constexpr int PITCH = 2 * BK + 16;       // 80
    constexpr int SA = BM * PITCH, SB = BN * PITCH, SST = SA + 2 * SB;

    extern __shared__ __align__(128) char smem[];
    const uint32_t sbase = s2u(smem);

    const int tid = threadIdx.x, lane = tid & 31, wid = tid >> 5;
    const int wm = wid & 3, wn = wid >> 2;
    const int m0 = blockIdx.y * BM;
    const int n0 = bRowOff + blockIdx.x * BN;
    const int c0 = blockIdx.x * BN;
    const int K = KTOT;

    float acc[MF][NF][4];
#pragma unroll
    for (int i = 0; i < MF; ++i)
#pragma unroll
        for (int j = 0; j < NF; ++j)
#pragma unroll
            for (int p = 0; p < 4; ++p) acc[i][j][p] = 0.f;

    auto load_stage = [&](int st, int kt) {
        const uint32_t base = sbase + st * SST;
        const int kk = kt * BK;
        constexpr int CPR = BK / 8;      // 4
#pragma unroll
        for (int c = tid; c < BM * CPR; c += 256) {
            const int row = c / CPR, cc = c % CPR;
            cpasync16(base + row * PITCH + cc * 16,
                      Ag + (size_t)(m0 + row) * K + kk + cc * 8);
        }
#pragma unroll
        for (int c = tid; c < BN * CPR; c += 256) {
            const int row = c / CPR, cc = c % CPR;
            const size_t g = (size_t)(n0 + row) * K + kk + cc * 8;
            const uint32_t s = row * PITCH + cc * 16;
            cpasync16(base + SA + s,      Bgh + g);
            cpasync16(base + SA + SB + s, Bgl + g);
        }
    };

    load_stage(0, 0);
    CP_COMMIT();
    load_stage(1, 1);
    CP_COMMIT();

    const int arow = wm * 32 + (lane & 15);
    const int brow = wn * WN + (lane & 7) + ((lane >> 4) << 3);
    const uint32_t aoff = (uint32_t)arow * PITCH + ((lane >> 4) << 4);
    const uint32_t boff = (uint32_t)brow * PITCH + (((lane >> 3) & 1) << 4);

    for (int kt = 0; kt < KCH; ++kt) {
        if (kt + STAGES - 1 < KCH) load_stage((kt + STAGES - 1) % STAGES, kt + STAGES - 1);
        CP_COMMIT();
        CP_WAIT2();
        __syncthreads();

        const uint32_t sb2 = sbase + (kt % STAGES) * SST;
        const uint32_t ab = sb2 + aoff;
        const uint32_t bb = sb2 + SA + boff;

#pragma unroll
        for (int ks = 0; ks < KS; ++ks) {
            uint32_t af[MF][4];
#pragma unroll
            for (int mf = 0; mf < MF; ++mf)
                ldsm4(af[mf], ab + mf * 16 * PITCH + ks * 32);
            uint32_t bh[NF][2], bl[NF][2];
#pragma unroll
            for (int nf2 = 0; nf2 < NF / 2; ++nf2) {
                const uint32_t off = bb + nf2 * 16 * PITCH + ks * 32;
                uint32_t t[4];
                ldsm4(t, off);
                bh[2 * nf2][0] = t[0]; bh[2 * nf2][1] = t[1];
                bh[2 * nf2 + 1][0] = t[2]; bh[2 * nf2 + 1][1] = t[3];
                ldsm4(t, off + SB);
                bl[2 * nf2][0] = t[0]; bl[2 * nf2][1] = t[1];
                bl[2 * nf2 + 1][0] = t[2]; bl[2 * nf2 + 1][1] = t[3];
            }
#pragma unroll
            for (int mf = 0; mf < MF; ++mf)
#pragma unroll
                for (int nf = 0; nf < NF; ++nf)
                    mma_bf16(acc[mf][nf], af[mf], bh[nf]);
#pragma unroll
            for (int mf = 0; mf < MF; ++mf)
#pragma unroll
                for (int nf = 0; nf < NF; ++nf)
                    mma_bf16(acc[mf][nf], af[mf], bl[nf]);
        }
        __syncthreads();
    }

    // Epilogue: o = (xh+xlo) + x0*(D+bias)
#pragma unroll
    for (int mf = 0; mf < MF; ++mf)
#pragma unroll
        for (int p = 0; p < 2; ++p) {
            const int m = m0 + wm * 32 + mf * 16 + (lane >> 2) + p * 8;
#pragma unroll
            for (int nf = 0; nf < NF; ++nf) {
                const int col = c0 + wn * WN + nf * 8 + (lane & 3) * 2;
                const size_t off = (size_t)m * DM + col;
                const float v0 = acc[mf][nf][p * 2];
                const float v1 = acc[mf][nf][p * 2 + 1];
                const float2 xz = *reinterpret_cast<const float2*>(x0 + off);
                const float2 bb2 = *reinterpret_cast<const float2*>(bias + col);
                const __nv_bfloat162 hv = *reinterpret_cast<const __nv_bfloat162*>(xh + off);
                const __nv_bfloat162 lv = *reinterpret_cast<const __nv_bfloat162*>(xl + off);
                const float xp0 = __bfloat162float(hv.x) + __bfloat162float(lv.x);
                const float xp1 = __bfloat162float(hv.y) + __bfloat162float(lv.y);
                const float o0 = fmaf(xz.x, v0 + bb2.x, xp0);
                const float o1 = fmaf(xz.y, v1 + bb2.y, xp1);
                if constexpr (MODE == 1) {
                    const __nv_bfloat16 h0 = __float2bfloat16(o0);
                    const __nv_bfloat16 h1 = __float2bfloat16(o1);
                    __nv_bfloat162 hp; hp.x = h0; hp.y = h1;
                    *reinterpret_cast<__nv_bfloat162*>(xh + off) = hp;
                    __nv_bfloat162 lp;
                    lp.x = __float2bfloat16(o0 - __bfloat162float(h0));
                    lp.y = __float2bfloat16(o1 - __bfloat162float(h1));
                    *reinterpret_cast<__nv_bfloat162*>(xl + off) = lp;
                } else {
                    *reinterpret_cast<float2*>(Cout + off) = make_float2(o0, o1);
                }
            }
        }
}

// ---------------------------------------------------------------------------
// Mix kernel (R14): vt=tanh(Y) -> v2=tanh(C vt) -> softmax gates -> bf16 wh
// ---------------------------------------------------------------------------
__global__ void __launch_bounds__(256) mix_kernel(const float* __restrict__ Y,
                                                  const float* __restrict__ Cl,
                                                  __nv_bfloat16* __restrict__ Wh)
{
    extern __shared__ float Cs[];          // 64 KB: Cs[(e*64+s)*64 + r] = C[e,r,s]
    __shared__ float vt[8][EE * RR];
    __shared__ float gs[8][EE];

    const int tid = threadIdx.x;
    for (int idx = tid; idx < EE * RR * RR; idx += 256) {
        int e = idx >> 12, rem = idx & 4095, s = rem >> 6, r = rem & 63;
        Cs[idx] = Cl[((size_t)e * RR + r) * RR + s];
    }
    __syncthreads();

    const int e = tid >> 6;
    const float* cp = Cs + e * (RR * RR) + (tid & 63);
    const int row0 = blockIdx.x * 64;

    for (int it = 0; it < 8; ++it) {
        const int row = row0 + it * 8;
#pragma unroll
        for (int q = 0; q < 8; ++q)
            vt[q][tid] = fast_tanh(Y[(size_t)(row + q) * NPAD + tid]);
        if (tid < 8) {
            const float* yr = Y + (size_t)(row + tid) * NPAD + EE * RR;
            const float l0 = yr[0], l1 = yr[1], l2 = yr[2], l3 = yr[3];
            const float mx = fmaxf(fmaxf(l0, l1), fmaxf(l2, l3));
            const float e0 = __expf(l0 - mx), e1 = __expf(l1 - mx);
            const float e2 = __expf(l2 - mx), e3 = __expf(l3 - mx);
            const float inv = __frcp_rn(e0 + e1 + e2 + e3);
            gs[tid][0] = e0 * inv; gs[tid][1] = e1 * inv;
            gs[tid][2] = e2 * inv; gs[tid][3] = e3 * inv;
        }
        __syncthreads();

        float a[8];
#pragma unroll
        for (int q = 0; q < 8; ++q) a[q] = 0.f;
#pragma unroll
        for (int s = 0; s < RR; ++s) {
            const float c = cp[s * RR];
#pragma unroll
            for (int q = 0; q < 8; ++q)
                a[q] = fmaf(c, vt[q][e * RR + s], a[q]);
        }
#pragma unroll
        for (int q = 0; q < 8; ++q) {
            const float w = gs[q][e] * fast_tanh(a[q]);
            Wh[(size_t)(row + q) * KW + tid] = __float2bfloat16(w);
        }
        __syncthreads();
    }
}

// ---------------------------------------------------------------------------
// Conversion (wide 16B stores) + weight packing
// ---------------------------------------------------------------------------
__global__ void conv_kernel(const float* __restrict__ x,
                            __nv_bfloat16* __restrict__ xh,
                            __nv_bfloat16* __restrict__ xl) {
    const size_t i = ((size_t)blockIdx.x * blockDim.x + threadIdx.x) * 8;
    const float4 v0 = *reinterpret_cast<const float4*>(x + i);
    const float4 v1 = *reinterpret_cast<const float4*>(x + i + 4);
    float vv[8] = {v0.x, v0.y, v0.z, v0.w, v1.x, v1.y, v1.z, v1.w};
    __align__(16) __nv_bfloat16 hh[8];
    __align__(16) __nv_bfloat16 ll[8];
#pragma unroll
    for (int q = 0; q < 8; ++q) {
        hh[q] = __float2bfloat16(vv[q]);
        ll[q] = __float2bfloat16(vv[q] - __bfloat162float(hh[q]));
    }
    *reinterpret_cast<uint4*>(xh + i) = *reinterpret_cast<uint4*>(hh);
    *reinterpret_cast<uint4*>(xl + i) = *reinterpret_cast<uint4*>(ll);
}

__global__ void pack_w1_kernel(const float* __restrict__ V, const float* __restrict__ gw,
                               __nv_bfloat16* __restrict__ Wh, __nv_bfloat16* __restrict__ Wl) {
    const int idx = blockIdx.x * blockDim.x + threadIdx.x;
    if (idx >= LL * NPAD * DM) return;
    const int i = idx / (NPAD * DM);
    const int rem = idx % (NPAD * DM);
    const int n = rem / DM, d = rem % DM;
    float v = 0.f;
    if (n < EE * RR)
        v = V[(((size_t)i * EE + (n >> 6)) * DM + d) * RR + (n & 63)];
    else if (n < EE * RR + EE)
        v = gw[(size_t)(n - EE * RR) * DM + d];
    const __nv_bfloat16 h = __float2bfloat16(v);
    Wh[idx] = h;
    Wl[idx] = __float2bfloat16(v - __bfloat162float(h));
}

__global__ void pack_u_kernel(const float* __restrict__ U,
                              __nv_bfloat16* __restrict__ Uh, __nv_bfloat16* __restrict__ Ul) {
    const int idx = blockIdx.x * blockDim.x + threadIdx.x;
    if (idx >= LL * DM * KW) return;
    const int i = idx / (DM * KW);
    const int rem = idx % (DM * KW);
    const int d = rem / KW, k = rem % KW;
    const float v = U[(((size_t)i * EE + (k >> 6)) * DM + d) * RR + (k & 63)];
    const __nv_bfloat16 h = __float2bfloat16(v);
    Uh[idx] = h;
    Ul[idx] = __float2bfloat16(v - __bfloat162float(h));
}

// ---------------------------------------------------------------------------
// Launch
// ---------------------------------------------------------------------------
extern "C" void kernel_launch(void* const* d_in, const int* in_sizes, int n_in,
                              void* d_out, int out_size) {
    const float* x0   = (const float*)d_in[0];
    const float* U    = (const float*)d_in[1];
    const float* V    = (const float*)d_in[2];
    const float* C    = (const float*)d_in[3];
    const float* gw   = (const float*)d_in[4];
    const float* bias = (const float*)d_in[5];
    float* out = (float*)d_out;

    float* Y = nullptr;
    __nv_bfloat16 *xh, *xl, *wh, *w1h, *w1l, *uh, *ul;
    cudaGetSymbolAddress((void**)&Y,   g_Y);
    cudaGetSymbolAddress((void**)&xh,  g_xh);
    cudaGetSymbolAddress((void**)&xl,  g_xlo);
    cudaGetSymbolAddress((void**)&wh,  g_wh);
    cudaGetSymbolAddress((void**)&w1h, g_W1h);
    cudaGetSymbolAddress((void**)&w1l, g_W1l);
    cudaGetSymbolAddress((void**)&uh,  g_Uh);
    cudaGetSymbolAddress((void**)&ul,  g_Ul);

    // GEMM1: 2 stages * (2*128*144 + 2*64*144) = 110592 B -> 2 CTAs/SM
    // GEMM2: 3 stages * (128*80 + 2*128*80)    =  92160 B -> 2 CTAs/SM
    constexpr int SMEM1 = 2 * (2 * 128 * 144 + 2 * 64 * 144);
    constexpr int SMEM2 = 3 * (128 * 80 + 2 * 128 * 80);
    cudaFuncSetAttribute((const void*)gemm1_bf16,
                         cudaFuncAttributeMaxDynamicSharedMemorySize, SMEM1);
    cudaFuncSetAttribute((const void*)gemm2_bf16<1>,
                         cudaFuncAttributeMaxDynamicSharedMemorySize, SMEM2);
    cudaFuncSetAttribute((const void*)gemm2_bf16<2>,
                         cudaFuncAttributeMaxDynamicSharedMemorySize, SMEM2);
    cudaFuncSetAttribute((const void*)mix_kernel,
                         cudaFuncAttributeMaxDynamicSharedMemorySize, EE * RR * RR * 4);

    // Pack weights + initial x conversion
    pack_w1_kernel<<<(LL * NPAD * DM + 255) / 256, 256>>>(V, gw, w1h, w1l);
    pack_u_kernel<<<(LL * DM * KW + 255) / 256, 256>>>(U, uh, ul);
    conv_kernel<<<(BSZ * DM / 8) / 256, 256>>>(x0, xh, xl);

    for (int i = 0; i < LL; ++i) {
        // GEMM1: Y[B,320] = x @ [V|gate]^T   (bf16 3-term, R14-proven)
        gemm1_bf16<<<dim3(NPAD / 64, BSZ / 128), 256, SMEM1>>>(
            xh, xl, w1h, w1l, i * NPAD, Y);

        // Mix: tanh -> C -> tanh -> softmax gates -> bf16 wh
        mix_kernel<<<BSZ / 64, 256, EE * RR * RR * 4>>>(
            Y, C + (size_t)i * EE * RR * RR, wh);

        // GEMM2 + fused epilogue: x_{l+1} = (xh+xlo) + x0*(wh @ (Uh+Ul)^T + bias)
        if (i < LL - 1) {
            gemm2_bf16<1><<<dim3(DM / 128, BSZ / 128), 256, SMEM2>>>(
                wh, uh, ul, i * DM,
                nullptr, x0, bias + (size_t)i * DM, xh, xl);
        } else {
            gemm2_bf16<2><<<dim3(DM / 128, BSZ / 128), 256, SMEM2>>>(
                wh, uh, ul, i * DM,
                out, x0, bias + (size_t)i * DM, xh, xl);
        }
    }
}

// round 17
// speedup vs baseline: 1.2541x; 1.0354x over previous
#include <cuda_runtime.h>
#include <cuda_bf16.h>
#include <cstdint>
#include <cstddef>

// Problem constants
#define BSZ   16384
#define DM    1024
#define RR    64
#define EE    4
#define LL    3
#define NPAD  320     // 256 V cols + 4 gate cols, padded to 5*64
#define KW    256     // E*R

// ---------------------------------------------------------------------------
// Static device buffers (all bf16)
// ---------------------------------------------------------------------------
__device__ __align__(256) __nv_bfloat16  g_xh[(size_t)BSZ * DM];      // bf16 hi of x_l
__device__ __align__(256) __nv_bfloat16  g_xlo[(size_t)BSZ * DM];     // bf16 lo of x_l
__device__ __align__(256) float          g_Y[(size_t)BSZ * NPAD];
__device__ __align__(256) __nv_bfloat16  g_wh[(size_t)BSZ * KW];      // bf16 w (rounded)
__device__ __align__(256) __nv_bfloat16  g_W1h[LL * NPAD * DM];       // [n][d] rows
__device__ __align__(256) __nv_bfloat16  g_W1l[LL * NPAD * DM];
__device__ __align__(256) __nv_bfloat16  g_Uh[LL * DM * KW];          // [d][k] rows
__device__ __align__(256) __nv_bfloat16  g_Ul[LL * DM * KW];

// ---------------------------------------------------------------------------
// PTX helpers (baseline ISA only)
// ---------------------------------------------------------------------------
__device__ __forceinline__ uint32_t s2u(const void* p) {
    uint32_t a;
    asm("{ .reg .u64 t; cvta.to.shared.u64 t, %1; cvt.u32.u64 %0, t; }" : "=r"(a) : "l"(p));
    return a;
}
__device__ __forceinline__ void cpasync16(uint32_t dst, const void* src) {
    asm volatile("cp.async.cg.shared.global [%0], [%1], 16;" :: "r"(dst), "l"(src) : "memory");
}
#define CP_COMMIT() asm volatile("cp.async.commit_group;" ::: "memory")
#define CP_WAIT1()  asm volatile("cp.async.wait_group 1;" ::: "memory")
#define CP_WAIT2()  asm volatile("cp.async.wait_group 2;" ::: "memory")

__device__ __forceinline__ void ldsm4(uint32_t* r, uint32_t addr) {
    asm volatile("ldmatrix.sync.aligned.m8n8.x4.shared.b16 {%0,%1,%2,%3}, [%4];"
                 : "=r"(r[0]), "=r"(r[1]), "=r"(r[2]), "=r"(r[3]) : "r"(addr));
}
__device__ __forceinline__ void mma_bf16(float* c, const uint32_t* a, const uint32_t* b) {
    asm volatile(
        "mma.sync.aligned.m16n8k16.row.col.f32.bf16.bf16.f32 "
        "{%0,%1,%2,%3}, {%4,%5,%6,%7}, {%8,%9}, {%0,%1,%2,%3};"
        : "+f"(c[0]), "+f"(c[1]), "+f"(c[2]), "+f"(c[3])
        : "r"(a[0]), "r"(a[1]), "r"(a[2]), "r"(a[3]), "r"(b[0]), "r"(b[1]));
}

// FMA-only tanh (no MUFU)
__device__ __forceinline__ float fast_tanh(float x) {
    float ax = fminf(fabsf(x), 9.0f);
    float z = ax * 2.885390082f;
    float k2 = z + 12582912.0f;
    int   ki = __float_as_int(k2) - 0x4B400000;
    float f  = z - (k2 - 12582912.0f);
    float p = 1.3333558e-3f;
    p = fmaf(p, f, 9.6181291e-3f);
    p = fmaf(p, f, 5.5504109e-2f);
    p = fmaf(p, f, 2.4022651e-1f);
    p = fmaf(p, f, 6.9314718e-1f);
    p = fmaf(p, f, 1.0f);
    float E = p * __int_as_float((ki + 127) << 23);
    float d = E + 1.0f;
    float r = __int_as_float(0x7EF311C3 - __float_as_int(d));
    r = r * fmaf(-d, r, 2.0f);
    r = r * fmaf(-d, r, 2.0f);
    r = r * fmaf(-d, r, 2.0f);
    float t = fmaf(-2.0f, r, 1.0f);
    return copysignf(t, x);
}

// ---------------------------------------------------------------------------
// GEMM1: bf16 3-term, BM=64 re-tile for wave quantization.
// 128 threads (4 warps: 2M x 2N), per-warp tile 32x32 (identical shape to the
// proven config). BK=64 (pitch 144), 2-stage cp.async, 3 CTAs/SM.
// Grid 5 x 256 = 1280 CTAs on 444 slots = 2.88 waves (96% util vs 72%).
// ---------------------------------------------------------------------------
__global__ void __launch_bounds__(128, 3)
gemm1_bf16(const __nv_bfloat16* __restrict__ Agh, const __nv_bfloat16* __restrict__ Agl,
           const __nv_bfloat16* __restrict__ Bgh, const __nv_bfloat16* __restrict__ Bgl,
           int bRowOff, float* __restrict__ Cout)
{
    constexpr int BM = 64, BN = 64, WN = 32, BK = 64, KTOT = DM;
    constexpr int MF = 2, NF = WN / 8, KS = BK / 16, KCH = KTOT / BK;
    constexpr int PITCH = 2 * BK + 16;       // 144
    constexpr int SA = BM * PITCH, SB = BN * PITCH, SST = 2 * SA + 2 * SB;
    constexpr int THREADS = 128;

    extern __shared__ __align__(128) char smem[];
    const uint32_t sbase = s2u(smem);

    const int tid = threadIdx.x, lane = tid & 31, wid = tid >> 5;
    const int wm = wid & 1, wn = wid >> 1;
    const int m0 = blockIdx.y * BM;
    const int n0 = bRowOff + blockIdx.x * BN;
    const int c0 = blockIdx.x * BN;
    const int K = KTOT;

    float acc[MF][NF][4];
#pragma unroll
    for (int i = 0; i < MF; ++i)
#pragma unroll
        for (int j = 0; j < NF; ++j)
#pragma unroll
            for (int p = 0; p < 4; ++p) acc[i][j][p] = 0.f;

    auto load_stage = [&](int st, int kt) {
        const uint32_t base = sbase + st * SST;
        const int kk = kt * BK;
        constexpr int CPR = BK / 8;       // 8
#pragma unroll
        for (int c = tid; c < BM * CPR; c += THREADS) {
            const int row = c / CPR, cc = c % CPR;
            const size_t g = (size_t)(m0 + row) * K + kk + cc * 8;
            const uint32_t s = row * PITCH + cc * 16;
            cpasync16(base + s,      Agh + g);
            cpasync16(base + SA + s, Agl + g);
        }
#pragma unroll
        for (int c = tid; c < BN * CPR; c += THREADS) {
            const int row = c / CPR, cc = c % CPR;
            const size_t g = (size_t)(n0 + row) * K + kk + cc * 8;
            const uint32_t s = row * PITCH + cc * 16;
            cpasync16(base + 2 * SA + s,      Bgh + g);
            cpasync16(base + 2 * SA + SB + s, Bgl + g);
        }
    };

    load_stage(0, 0);
    CP_COMMIT();

    const int arow = wm * 32 + (lane & 15);
    const int brow = wn * WN + (lane & 7) + ((lane >> 4) << 3);
    const uint32_t aoff = (uint32_t)arow * PITCH + ((lane >> 4) << 4);
    const uint32_t boff = (uint32_t)brow * PITCH + (((lane >> 3) & 1) << 4);

    for (int kt = 0; kt < KCH; ++kt) {
        if (kt + 1 < KCH) load_stage((kt + 1) & 1, kt + 1);
        CP_COMMIT();
        CP_WAIT1();
        __syncthreads();

        const uint32_t sb2 = sbase + (kt & 1) * SST;
        const uint32_t ab = sb2 + aoff;
        const uint32_t bb = sb2 + 2 * SA + boff;

#pragma unroll
        for (int ks = 0; ks < KS; ++ks) {
            uint32_t ah[MF][4], al[MF][4];
#pragma unroll
            for (int mf = 0; mf < MF; ++mf) {
                const uint32_t off = ab + mf * 16 * PITCH + ks * 32;
                ldsm4(ah[mf], off);
                ldsm4(al[mf], off + SA);
            }
            uint32_t bh[NF][2], bl[NF][2];
#pragma unroll
            for (int nf2 = 0; nf2 < NF / 2; ++nf2) {
                const uint32_t off = bb + nf2 * 16 * PITCH + ks * 32;
                uint32_t t[4];
                ldsm4(t, off);
                bh[2 * nf2][0] = t[0]; bh[2 * nf2][1] = t[1];
                bh[2 * nf2 + 1][0] = t[2]; bh[2 * nf2 + 1][1] = t[3];
                ldsm4(t, off + SB);
                bl[2 * nf2][0] = t[0]; bl[2 * nf2][1] = t[1];
                bl[2 * nf2 + 1][0] = t[2]; bl[2 * nf2 + 1][1] = t[3];
            }
#pragma unroll
            for (int mf = 0; mf < MF; ++mf)
#pragma unroll
                for (int nf = 0; nf < NF; ++nf) {
                    mma_bf16(acc[mf][nf], ah[mf], bh[nf]);
                    mma_bf16(acc[mf][nf], ah[mf], bl[nf]);
                    mma_bf16(acc[mf][nf], al[mf], bh[nf]);
                }
        }
        __syncthreads();
    }

#pragma unroll
    for (int mf = 0; mf < MF; ++mf)
#pragma unroll
        for (int p = 0; p < 2; ++p) {
            const int m = m0 + wm * 32 + mf * 16 + (lane >> 2) + p * 8;
#pragma unroll
            for (int nf = 0; nf < NF; ++nf) {
                const int col = c0 + wn * WN + nf * 8 + (lane & 3) * 2;
                *reinterpret_cast<float2*>(Cout + (size_t)m * NPAD + col) =
                    make_float2(acc[mf][nf][p * 2], acc[mf][nf][p * 2 + 1]);
            }
        }
}

// ---------------------------------------------------------------------------
// GEMM2 (R16): bf16 2-term (A single wh, B split Uh+Ul), 3-stage pipeline.
// BM=128, BN=128, WN=64, BK=32 (pitch 80), 3 stages (92160 B), 2 CTAs/SM.
// Epilogue: o = (xh+xlo) + x0*(D+bias); MODE 1 writes bf16 xh/xlo = split(o),
// MODE 2 writes fp32 o to Cout.
// ---------------------------------------------------------------------------
template <int MODE>
__global__ void __launch_bounds__(256, 2)
gemm2_bf16(const __nv_bfloat16* __restrict__ Ag,
           const __nv_bfloat16* __restrict__ Bgh, const __nv_bfloat16* __restrict__ Bgl,
           int bRowOff, float* __restrict__ Cout,
           const float* __restrict__ x0, const float* __restrict__ bias,
           __nv_bfloat16* __restrict__ xh, __nv_bfloat16* __restrict__ xl)
{
    constexpr int BM = 128, BN = 128, WN = 64, BK = 32, KTOT = KW, STAGES = 3;
    constexpr int MF = 2, NF = WN / 8, KS = BK / 16, KCH = KTOT / BK;
    constexpr int PITCH = 2 * BK + 16;       // 80
    constexpr int SA = BM * PITCH, SB = BN * PITCH, SST = SA + 2 * SB;

    extern __shared__ __align__(128) char smem[];
    const uint32_t sbase = s2u(smem);

    const int tid = threadIdx.x, lane = tid & 31, wid = tid >> 5;
    const int wm = wid & 3, wn = wid >> 2;
    const int m0 = blockIdx.y * BM;
    const int n0 = bRowOff + blockIdx.x * BN;
    const int c0 = blockIdx.x * BN;
    const int K = KTOT;

    float acc[MF][NF][4];
#pragma unroll
    for (int i = 0; i < MF; ++i)
#pragma unroll
        for (int j = 0; j < NF; ++j)
#pragma unroll
            for (int p = 0; p < 4; ++p) acc[i][j][p] = 0.f;

    auto load_stage = [&](int st, int kt) {
        const uint32_t base = sbase + st * SST;
        const int kk = kt * BK;
        constexpr int CPR = BK / 8;      // 4
#pragma unroll
        for (int c = tid; c < BM * CPR; c += 256) {
            const int row = c / CPR, cc = c % CPR;
            cpasync16(base + row * PITCH + cc * 16,
                      Ag + (size_t)(m0 + row) * K + kk + cc * 8);
        }
#pragma unroll
        for (int c = tid; c < BN * CPR; c += 256) {
            const int row = c / CPR, cc = c % CPR;
            const size_t g = (size_t)(n0 + row) * K + kk + cc * 8;
            const uint32_t s = row * PITCH + cc * 16;
            cpasync16(base + SA + s,      Bgh + g);
            cpasync16(base + SA + SB + s, Bgl + g);
        }
    };

    load_stage(0, 0);
    CP_COMMIT();
    load_stage(1, 1);
    CP_COMMIT();

    const int arow = wm * 32 + (lane & 15);
    const int brow = wn * WN + (lane & 7) + ((lane >> 4) << 3);
    const uint32_t aoff = (uint32_t)arow * PITCH + ((lane >> 4) << 4);
    const uint32_t boff = (uint32_t)brow * PITCH + (((lane >> 3) & 1) << 4);

    for (int kt = 0; kt < KCH; ++kt) {
        if (kt + STAGES - 1 < KCH) load_stage((kt + STAGES - 1) % STAGES, kt + STAGES - 1);
        CP_COMMIT();
        CP_WAIT2();
        __syncthreads();

        const uint32_t sb2 = sbase + (kt % STAGES) * SST;
        const uint32_t ab = sb2 + aoff;
        const uint32_t bb = sb2 + SA + boff;

#pragma unroll
        for (int ks = 0; ks < KS; ++ks) {
            uint32_t af[MF][4];
#pragma unroll
            for (int mf = 0; mf < MF; ++mf)
                ldsm4(af[mf], ab + mf * 16 * PITCH + ks * 32);
            uint32_t bh[NF][2], bl[NF][2];
#pragma unroll
            for (int nf2 = 0; nf2 < NF / 2; ++nf2) {
                const uint32_t off = bb + nf2 * 16 * PITCH + ks * 32;
                uint32_t t[4];
                ldsm4(t, off);
                bh[2 * nf2][0] = t[0]; bh[2 * nf2][1] = t[1];
                bh[2 * nf2 + 1][0] = t[2]; bh[2 * nf2 + 1][1] = t[3];
                ldsm4(t, off + SB);
                bl[2 * nf2][0] = t[0]; bl[2 * nf2][1] = t[1];
                bl[2 * nf2 + 1][0] = t[2]; bl[2 * nf2 + 1][1] = t[3];
            }
#pragma unroll
            for (int mf = 0; mf < MF; ++mf)
#pragma unroll
                for (int nf = 0; nf < NF; ++nf)
                    mma_bf16(acc[mf][nf], af[mf], bh[nf]);
#pragma unroll
            for (int mf = 0; mf < MF; ++mf)
#pragma unroll
                for (int nf = 0; nf < NF; ++nf)
                    mma_bf16(acc[mf][nf], af[mf], bl[nf]);
        }
        __syncthreads();
    }

    // Epilogue: o = (xh+xlo) + x0*(D+bias)
#pragma unroll
    for (int mf = 0; mf < MF; ++mf)
#pragma unroll
        for (int p = 0; p < 2; ++p) {
            const int m = m0 + wm * 32 + mf * 16 + (lane >> 2) + p * 8;
#pragma unroll
            for (int nf = 0; nf < NF; ++nf) {
                const int col = c0 + wn * WN + nf * 8 + (lane & 3) * 2;
                const size_t off = (size_t)m * DM + col;
                const float v0 = acc[mf][nf][p * 2];
                const float v1 = acc[mf][nf][p * 2 + 1];
                const float2 xz = *reinterpret_cast<const float2*>(x0 + off);
                const float2 bb2 = *reinterpret_cast<const float2*>(bias + col);
                const __nv_bfloat162 hv = *reinterpret_cast<const __nv_bfloat162*>(xh + off);
                const __nv_bfloat162 lv = *reinterpret_cast<const __nv_bfloat162*>(xl + off);
                const float xp0 = __bfloat162float(hv.x) + __bfloat162float(lv.x);
                const float xp1 = __bfloat162float(hv.y) + __bfloat162float(lv.y);
                const float o0 = fmaf(xz.x, v0 + bb2.x, xp0);
                const float o1 = fmaf(xz.y, v1 + bb2.y, xp1);
                if constexpr (MODE == 1) {
                    const __nv_bfloat16 h0 = __float2bfloat16(o0);
                    const __nv_bfloat16 h1 = __float2bfloat16(o1);
                    __nv_bfloat162 hp; hp.x = h0; hp.y = h1;
                    *reinterpret_cast<__nv_bfloat162*>(xh + off) = hp;
                    __nv_bfloat162 lp;
                    lp.x = __float2bfloat16(o0 - __bfloat162float(h0));
                    lp.y = __float2bfloat16(o1 - __bfloat162float(h1));
                    *reinterpret_cast<__nv_bfloat162*>(xl + off) = lp;
                } else {
                    *reinterpret_cast<float2*>(Cout + off) = make_float2(o0, o1);
                }
            }
        }
}

// ---------------------------------------------------------------------------
// Mix kernel (R14): vt=tanh(Y) -> v2=tanh(C vt) -> softmax gates -> bf16 wh
// ---------------------------------------------------------------------------
__global__ void __launch_bounds__(256) mix_kernel(const float* __restrict__ Y,
                                                  const float* __restrict__ Cl,
                                                  __nv_bfloat16* __restrict__ Wh)
{
    extern __shared__ float Cs[];          // 64 KB: Cs[(e*64+s)*64 + r] = C[e,r,s]
    __shared__ float vt[8][EE * RR];
    __shared__ float gs[8][EE];

    const int tid = threadIdx.x;
    for (int idx = tid; idx < EE * RR * RR; idx += 256) {
        int e = idx >> 12, rem = idx & 4095, s = rem >> 6, r = rem & 63;
        Cs[idx] = Cl[((size_t)e * RR + r) * RR + s];
    }
    __syncthreads();

    const int e = tid >> 6;
    const float* cp = Cs + e * (RR * RR) + (tid & 63);
    const int row0 = blockIdx.x * 64;

    for (int it = 0; it < 8; ++it) {
        const int row = row0 + it * 8;
#pragma unroll
        for (int q = 0; q < 8; ++q)
            vt[q][tid] = fast_tanh(Y[(size_t)(row + q) * NPAD + tid]);
        if (tid < 8) {
            const float* yr = Y + (size_t)(row + tid) * NPAD + EE * RR;
            const float l0 = yr[0], l1 = yr[1], l2 = yr[2], l3 = yr[3];
            const float mx = fmaxf(fmaxf(l0, l1), fmaxf(l2, l3));
            const float e0 = __expf(l0 - mx), e1 = __expf(l1 - mx);
            const float e2 = __expf(l2 - mx), e3 = __expf(l3 - mx);
            const float inv = __frcp_rn(e0 + e1 + e2 + e3);
            gs[tid][0] = e0 * inv; gs[tid][1] = e1 * inv;
            gs[tid][2] = e2 * inv; gs[tid][3] = e3 * inv;
        }
        __syncthreads();

        float a[8];
#pragma unroll
        for (int q = 0; q < 8; ++q) a[q] = 0.f;
#pragma unroll
        for (int s = 0; s < RR; ++s) {
            const float c = cp[s * RR];
#pragma unroll
            for (int q = 0; q < 8; ++q)
                a[q] = fmaf(c, vt[q][e * RR + s], a[q]);
        }
#pragma unroll
        for (int q = 0; q < 8; ++q) {
            const float w = gs[q][e] * fast_tanh(a[q]);
            Wh[(size_t)(row + q) * KW + tid] = __float2bfloat16(w);
        }
        __syncthreads();
    }
}

// ---------------------------------------------------------------------------
// Conversion (wide 16B stores) + weight packing
// ---------------------------------------------------------------------------
__global__ void conv_kernel(const float* __restrict__ x,
                            __nv_bfloat16* __restrict__ xh,
                            __nv_bfloat16* __restrict__ xl) {
    const size_t i = ((size_t)blockIdx.x * blockDim.x + threadIdx.x) * 8;
    const float4 v0 = *reinterpret_cast<const float4*>(x + i);
    const float4 v1 = *reinterpret_cast<const float4*>(x + i + 4);
    float vv[8] = {v0.x, v0.y, v0.z, v0.w, v1.x, v1.y, v1.z, v1.w};
    __align__(16) __nv_bfloat16 hh[8];
    __align__(16) __nv_bfloat16 ll[8];
#pragma unroll
    for (int q = 0; q < 8; ++q) {
        hh[q] = __float2bfloat16(vv[q]);
        ll[q] = __float2bfloat16(vv[q] - __bfloat162float(hh[q]));
    }
    *reinterpret_cast<uint4*>(xh + i) = *reinterpret_cast<uint4*>(hh);
    *reinterpret_cast<uint4*>(xl + i) = *reinterpret_cast<uint4*>(ll);
}

__global__ void pack_w1_kernel(const float* __restrict__ V, const float* __restrict__ gw,
                               __nv_bfloat16* __restrict__ Wh, __nv_bfloat16* __restrict__ Wl) {
    const int idx = blockIdx.x * blockDim.x + threadIdx.x;
    if (idx >= LL * NPAD * DM) return;
    const int i = idx / (NPAD * DM);
    const int rem = idx % (NPAD * DM);
    const int n = rem / DM, d = rem % DM;
    float v = 0.f;
    if (n < EE * RR)
        v = V[(((size_t)i * EE + (n >> 6)) * DM + d) * RR + (n & 63)];
    else if (n < EE * RR + EE)
        v = gw[(size_t)(n - EE * RR) * DM + d];
    const __nv_bfloat16 h = __float2bfloat16(v);
    Wh[idx] = h;
    Wl[idx] = __float2bfloat16(v - __bfloat162float(h));
}

__global__ void pack_u_kernel(const float* __restrict__ U,
                              __nv_bfloat16* __restrict__ Uh, __nv_bfloat16* __restrict__ Ul) {
    const int idx = blockIdx.x * blockDim.x + threadIdx.x;
    if (idx >= LL * DM * KW) return;
    const int i = idx / (DM * KW);
    const int rem = idx % (DM * KW);
    const int d = rem / KW, k = rem % KW;
    const float v = U[(((size_t)i * EE + (k >> 6)) * DM + d) * RR + (k & 63)];
    const __nv_bfloat16 h = __float2bfloat16(v);
    Uh[idx] = h;
    Ul[idx] = __float2bfloat16(v - __bfloat162float(h));
}

// ---------------------------------------------------------------------------
// Launch
// ---------------------------------------------------------------------------
extern "C" void kernel_launch(void* const* d_in, const int* in_sizes, int n_in,
                              void* d_out, int out_size) {
    const float* x0   = (const float*)d_in[0];
    const float* U    = (const float*)d_in[1];
    const float* V    = (const float*)d_in[2];
    const float* C    = (const float*)d_in[3];
    const float* gw   = (const float*)d_in[4];
    const float* bias = (const float*)d_in[5];
    float* out = (float*)d_out;

    float* Y = nullptr;
    __nv_bfloat16 *xh, *xl, *wh, *w1h, *w1l, *uh, *ul;
    cudaGetSymbolAddress((void**)&Y,   g_Y);
    cudaGetSymbolAddress((void**)&xh,  g_xh);
    cudaGetSymbolAddress((void**)&xl,  g_xlo);
    cudaGetSymbolAddress((void**)&wh,  g_wh);
    cudaGetSymbolAddress((void**)&w1h, g_W1h);
    cudaGetSymbolAddress((void**)&w1l, g_W1l);
    cudaGetSymbolAddress((void**)&uh,  g_Uh);
    cudaGetSymbolAddress((void**)&ul,  g_Ul);

    // GEMM1: 2 stages * (2*64*144 + 2*64*144) = 73728 B -> 3 CTAs/SM (128 thr)
    // GEMM2: 3 stages * (128*80 + 2*128*80)   = 92160 B -> 2 CTAs/SM
    constexpr int SMEM1 = 2 * (2 * 64 * 144 + 2 * 64 * 144);
    constexpr int SMEM2 = 3 * (128 * 80 + 2 * 128 * 80);
    cudaFuncSetAttribute((const void*)gemm1_bf16,
                         cudaFuncAttributeMaxDynamicSharedMemorySize, SMEM1);
    cudaFuncSetAttribute((const void*)gemm2_bf16<1>,
                         cudaFuncAttributeMaxDynamicSharedMemorySize, SMEM2);
    cudaFuncSetAttribute((const void*)gemm2_bf16<2>,
                         cudaFuncAttributeMaxDynamicSharedMemorySize, SMEM2);
    cudaFuncSetAttribute((const void*)mix_kernel,
                         cudaFuncAttributeMaxDynamicSharedMemorySize, EE * RR * RR * 4);

    // Pack weights + initial x conversion
    pack_w1_kernel<<<(LL * NPAD * DM + 255) / 256, 256>>>(V, gw, w1h, w1l);
    pack_u_kernel<<<(LL * DM * KW + 255) / 256, 256>>>(U, uh, ul);
    conv_kernel<<<(BSZ * DM / 8) / 256, 256>>>(x0, xh, xl);

    for (int i = 0; i < LL; ++i) {
        // GEMM1: Y[B,320] = x @ [V|gate]^T   (bf16 3-term, BM=64 re-tile)
        gemm1_bf16<<<dim3(NPAD / 64, BSZ / 64), 128, SMEM1>>>(
            xh, xl, w1h, w1l, i * NPAD, Y);

        // Mix: tanh -> C -> tanh -> softmax gates -> bf16 wh
        mix_kernel<<<BSZ / 64, 256, EE * RR * RR * 4>>>(
            Y, C + (size_t)i * EE * RR * RR, wh);

        // GEMM2 + fused epilogue: x_{l+1} = (xh+xlo) + x0*(wh @ (Uh+Ul)^T + bias)
        if (i < LL - 1) {
            gemm2_bf16<1><<<dim3(DM / 128, BSZ / 128), 256, SMEM2>>>(
                wh, uh, ul, i * DM,
                nullptr, x0, bias + (size_t)i * DM, xh, xl);
        } else {
            gemm2_bf16<2><<<dim3(DM / 128, BSZ / 128), 256, SMEM2>>>(
                wh, uh, ul, i * DM,
                out, x0, bias + (size_t)i * DM, xh, xl);
        }
    }
}